// round 2
// baseline (speedup 1.0000x reference)
#include <cuda_runtime.h>

#define BB 64
#define TT 1024
#define NN 48
#define CH 16
#define PF 8

// Scratch (no cudaMalloc allowed): per-batch log_norm and per-(batch,chunk) score partials.
__device__ float g_lognorm[BB];
__device__ float g_part[BB][CH];

__global__ __launch_bounds__(96) void crf_main(
    const float* __restrict__ y_true,
    const float* __restrict__ y_pred,
    const int*   __restrict__ spk,
    const float* __restrict__ tr0,
    const float* __restrict__ tr1,
    const float* __restrict__ tr2)
{
    __shared__ __align__(16) float sbuf[7500];  // 30 KB, overlaid per branch
    const int tid = threadIdx.x;

    if (blockIdx.x < BB) {
        // ---------------- Forward recursion: one block per batch ----------------
        const int b = blockIdx.x;
        const int p = tid & 1;       // i-half: 0 -> rows 0..23, 1 -> rows 24..47
        const int j = tid >> 1;      // output column 0..47

        float* Esh = sbuf;           // exp(TRANS): 3 matrices, row stride 50 (bank-conflict-free)
        float* vsh = sbuf + 7200;    // double-buffered state vector v[2][48]

        for (int idx = tid; idx < 3 * 48 * 48; idx += 96) {
            int k  = idx / 2304;
            int rc = idx - k * 2304;
            int r  = rc / 48;
            int cc = rc - r * 48;
            const float* Tk = (k == 0) ? tr0 : (k == 1) ? tr1 : tr2;
            Esh[k * 2400 + r * 50 + cc] = __expf(Tk[rc]);
        }

        const float* ypb = y_pred + b * TT * NN;
        const int*   spb = spk + b * (TT - 1);

        if (tid < 48) vsh[tid] = __expf(ypb[tid]);   // v_0 = exp(state_0), shift m = 0

        // Register prefetch ring for emissions + transition selectors.
        float ebuf[PF];
        int   kbuf[PF];
        #pragma unroll
        for (int u = 0; u < PF; u++) {
            ebuf[u] = ypb[(1 + u) * NN + j];
            kbuf[u] = spb[u];
        }
        __syncthreads();

        float m = 0.f;
        int cur = 0;
        for (int blk = 0; blk < (TT + PF - 1) / PF; blk++) {
            #pragma unroll
            for (int u = 0; u < PF; u++) {
                int t = 1 + blk * PF + u;
                if (t < TT) {
                    int   kk   = kbuf[u];
                    float emit = ebuf[u];
                    // prefetch PF steps ahead (clamped at the tail)
                    int tp   = t + PF;
                    int tpc  = (tp < TT) ? tp : (TT - 1);
                    int sidx = tp - 1; if (sidx > TT - 2) sidx = TT - 2;
                    ebuf[u] = ypb[tpc * NN + j];
                    kbuf[u] = spb[sidx];

                    float* vc = vsh + cur * 48;
                    float v0  = vc[0];
                    float pe  = __expf(emit);           // off critical path (prefetched operand)
                    float r   = __fdividef(1.f, v0);    // per-step renormalization factor
                    float rp  = r * pe;                 // ready before the dot completes

                    const float* Ekj = Esh + kk * 2400 + (24 * p) * 50 + j;

                    float vv[24];
                    #pragma unroll
                    for (int q = 0; q < 6; q++) {
                        float4 f4 = *(const float4*)(vc + 24 * p + 4 * q);
                        vv[4*q] = f4.x; vv[4*q+1] = f4.y; vv[4*q+2] = f4.z; vv[4*q+3] = f4.w;
                    }
                    float a0 = 0.f, a1 = 0.f, a2 = 0.f, a3 = 0.f;
                    #pragma unroll
                    for (int i = 0; i < 24; i += 4) {
                        a0 += vv[i]     * Ekj[(i    ) * 50];
                        a1 += vv[i + 1] * Ekj[(i + 1) * 50];
                        a2 += vv[i + 2] * Ekj[(i + 2) * 50];
                        a3 += vv[i + 3] * Ekj[(i + 3) * 50];
                    }
                    float dot = (a0 + a1) + (a2 + a3);
                    dot += __shfl_xor_sync(0xffffffffu, dot, 1);  // combine the two i-halves

                    float vn = dot * rp;
                    if (p == 0) vsh[(cur ^ 1) * 48 + j] = vn;
                    if (tid == 0) m += __logf(v0);
                    __syncthreads();
                    cur ^= 1;
                }
            }
        }
        if (tid == 0) {
            float s = 0.f;
            const float* vc = vsh + cur * 48;
            for (int q = 0; q < 48; q++) s += vc[q];
            g_lognorm[b] = m + __logf(s);
        }
    } else {
        // ---------------- Score reductions: (b, chunk) blocks, hidden under the chains ----------------
        int idx = blockIdx.x - BB;
        int b   = idx / CH;
        int c   = idx - b * CH;

        float* Ash  = sbuf;          // raw TRANS, 3*2304
        float* l1sh = sbuf + 6912;   // double-buffered l1 broadcast [2][48]
        float* red  = sbuf + 7008;   // 48-wide reduction scratch

        for (int q = tid; q < 3 * 2304; q += 96) {
            int k  = q / 2304;
            int rc = q - k * 2304;
            const float* Tk = (k == 0) ? tr0 : (k == 1) ? tr1 : tr2;
            Ash[q] = Tk[rc];
        }

        const float* ytb = y_true + b * TT * NN;
        const float* ypb = y_pred + b * TT * NN;
        const int*   spb = spk + b * (TT - 1);

        const int LEN = (TT - 1 + CH - 1) / CH;   // 64
        int tA  = c * LEN;
        int tBn = tA + LEN; if (tBn > TT - 1) tBn = TT - 1;

        const bool act = (tid < 48);
        const int  j   = tid;
        float pacc = 0.f, tacc = 0.f;

        for (int t = tA; t < tBn; t++) {
            float l1 = 0.f, l2 = 0.f, yp = 0.f;
            if (act) {
                l1 = ytb[t * NN + j];
                l2 = ytb[(t + 1) * NN + j];
                yp = ypb[t * NN + j];
                l1sh[(t & 1) * 48 + j] = l1;
            }
            int kk = spb[t];
            __syncthreads();
            if (act) {
                const float* Akj = Ash + kk * 2304 + j;
                const float* l1s = l1sh + (t & 1) * 48;
                float u0 = 0.f, u1 = 0.f;
                #pragma unroll
                for (int i = 0; i < 48; i += 2) {
                    u0 += l1s[i]     * Akj[(i    ) * 48];
                    u1 += l1s[i + 1] * Akj[(i + 1) * 48];
                }
                tacc += (u0 + u1) * l2;
                pacc += yp * l1;
            }
        }
        if (c == CH - 1 && act) {   // point-score term for t = T-1
            pacc += ypb[(TT - 1) * NN + j] * ytb[(TT - 1) * NN + j];
        }
        if (act) red[j] = pacc + tacc;
        __syncthreads();
        if (tid == 0) {
            float s = 0.f;
            for (int q = 0; q < 48; q++) s += red[q];  // fixed order -> deterministic
            g_part[b][c] = s;
        }
    }
}

__global__ void crf_combine(float* __restrict__ out)
{
    int b = threadIdx.x;
    if (b < BB) {
        float q = 0.f;
        for (int c = 0; c < CH; c++) q += g_part[b][c];
        out[b] = g_lognorm[b] - q;
    }
}

extern "C" void kernel_launch(void* const* d_in, const int* in_sizes, int n_in,
                              void* d_out, int out_size)
{
    const float* y_true = (const float*)d_in[0];
    const float* y_pred = (const float*)d_in[1];
    const int*   spkseq = (const int*)d_in[2];
    const float* tr0    = (const float*)d_in[3];
    const float* tr1    = (const float*)d_in[4];
    const float* tr2    = (const float*)d_in[5];

    crf_main<<<BB + BB * CH, 96>>>(y_true, y_pred, spkseq, tr0, tr1, tr2);
    crf_combine<<<1, 64>>>((float*)d_out);
}